// round 2
// baseline (speedup 1.0000x reference)
#include <cuda_runtime.h>
#include <cuda_fp16.h>
#include <cstdint>

// Problem constants (fixed by the dataset)
#define NL0 8000
#define NL1 4000
#define NL2 2000
#define NTOT 14000
#define FDIM 128
#define NCOL 384

static constexpr float ADJ_SCALE = 4096.0f;
static constexpr float INV_SCALE = 1.0f / 4096.0f;

// ---------------- device scratch (static, no allocations) ----------------
__device__ __half g_wcat[3 * FDIM * NCOL]; // per-j: [128][384] with col block i
__device__ __half g_T[NTOT * NCOL];        // T_j = h_j @ Wcat_j
__device__ __half g_Y[NTOT * NCOL];        // gathered/scattered B operand
__device__ float  g_Z[NTOT * NCOL];        // big GEMM output (atomic-accumulated)
__device__ int    g_inv0[NL0];
__device__ int    g_inv1[NL1];

// ---------------- prep: Wcat fp16, inv init, zero Z ----------------
__global__ void k_prep(const float* __restrict__ Ws) {
    int t = blockIdx.x * blockDim.x + threadIdx.x;
    if (t < 3 * FDIM * NCOL) {
        int j = t / 49152;
        int rem = t % 49152;
        int k = rem / 384;
        int col = rem % 384;
        int i = col >> 7;
        int c = col & 127;
        g_wcat[t] = __float2half(Ws[(((size_t)(i * 3 + j) * 128) + k) * 128 + c]);
    }
    if (t < NL0) g_inv0[t] = -1;
    if (t < NL1) g_inv1[t] = -1;
    if (t < (NTOT * NCOL) / 4) {
        ((float4*)g_Z)[t] = make_float4(0.f, 0.f, 0.f, 0.f);
    }
}

__global__ void k_scatter_inv(const int* __restrict__ idx0, const int* __restrict__ idx1) {
    int t = blockIdx.x * blockDim.x + threadIdx.x;
    if (t < NL1) g_inv0[idx0[t]] = t;
    if (t < NL2) g_inv1[idx1[t]] = t;
}

// Gather T -> Y (one 16B chunk per thread)
__global__ void k_gather_y(const int* __restrict__ idx0, const int* __restrict__ idx1) {
    int tid = blockIdx.x * blockDim.x + threadIdx.x;
    if (tid >= NTOT * 3 * 16) return;
    int seg = tid & 15;
    int rest = tid >> 4;
    int j = rest % 3;
    int rg = rest / 3;
    int i, r;
    if (rg < NL0)            { i = 0; r = rg; }
    else if (rg < NL0 + NL1) { i = 1; r = rg - NL0; }
    else                     { i = 2; r = rg - NL0 - NL1; }
    int s = -1;
    if (i == 0) {
        if (j == 0) s = r;
        else if (j == 1) s = g_inv0[r];
        else { int t0 = g_inv0[r]; s = (t0 >= 0) ? g_inv1[t0] : -1; }
    } else if (i == 1) {
        if (j == 0) s = idx0[r];
        else if (j == 1) s = r;
        else s = g_inv1[r];
    } else {
        if (j == 0) s = idx0[idx1[r]];
        else if (j == 1) s = idx1[r];
        else s = r;
    }
    uint4 v = make_uint4(0u, 0u, 0u, 0u);
    if (s >= 0) {
        int srow = (j == 0 ? 0 : (j == 1 ? NL0 : NL0 + NL1)) + s;
        v = *(const uint4*)(g_T + (size_t)srow * NCOL + i * 128 + seg * 8);
    }
    *(uint4*)(g_Y + (size_t)rg * NCOL + j * 128 + seg * 8) = v;
}

// ---------------- GEMM: C[MxN=384] = (scale*A_fp32)[MxK] * B_fp16[KxN=384] ----------------
// A converted fp32->fp16 in-kernel. Split-K: uniform ~2016-col chunks, fp32 atomicAdd (mode 1)
// or direct fp16 store (mode 0, single chunk).
struct GemmSeg { const float* A; const __half* B; char* C; int M, K, mtiles, kchunks, ctaStart; };
struct GemmCfg { GemmSeg seg[3]; float scale; int mode; };

#define BM 64
#define BK 32
#define KCH 2016
#define APITCH 40   // halves per A smem row (pad 8)
#define BPITCH 392  // halves per B smem row (pad 8)
#define STG_HALVES (BM * APITCH + BK * BPITCH)  // 2560 + 12544 = 15104
#define SMEM_BYTES (3 * STG_HALVES * 2)         // 90624

__device__ __forceinline__ void cp16(__half* dst, const void* src, bool full) {
    unsigned d = (unsigned)__cvta_generic_to_shared(dst);
    int n = full ? 16 : 0;
    asm volatile("cp.async.cg.shared.global [%0], [%1], 16, %2;\n" :: "r"(d), "l"(src), "r"(n));
}

__global__ void __launch_bounds__(512, 1) k_gemm(GemmCfg cfg) {
    extern __shared__ __align__(16) char smem_raw[];
    __half* smem = (__half*)smem_raw;

    int tid = threadIdx.x;
    int bx = blockIdx.x;
    int s = 2;
    if (bx < cfg.seg[1].ctaStart) s = 0;
    else if (bx < cfg.seg[2].ctaStart) s = 1;
    GemmSeg sg = cfg.seg[s];
    int local = bx - sg.ctaStart;
    int mtile = local / sg.kchunks;
    int kc = local - mtile * sg.kchunks;
    int row0 = mtile * BM;
    int M = sg.M, K = sg.K;
    int k0 = kc * KCH;
    int kend = min(k0 + KCH, K);
    int KT = (kend - k0 + BK - 1) / BK;
    const float* A = sg.A;
    const __half* B = sg.B;
    float scale = cfg.scale;

    int lane = tid & 31, wid = tid >> 5;
    int wm = wid >> 2, wn = wid & 3;    // 4 x 4 warp grid; warp tile 16x96

    // A load coords: 64x32 fp32 tile, 512 threads, 1 float4 each
    int arow = tid >> 3;
    int acg = (tid & 7) * 4;
    // B load coords: 32x384 halves, 3 x 16B chunk per thread
    int br[3], bseg[3];
#pragma unroll
    for (int it = 0; it < 3; ++it) { int c = tid + it * 512; br[it] = c / 48; bseg[it] = c % 48; }

    auto loadA = [&](int kt, float4& v) {
        int grow = row0 + arow;
        int gcol = k0 + kt * BK + acg;
        v = make_float4(0.f, 0.f, 0.f, 0.f);
        if (grow < M && gcol < kend) v = *(const float4*)(A + (size_t)grow * K + gcol);
    };
    auto stsA = [&](int st, const float4& v) {
        __half* as = smem + st * STG_HALVES;
        uint2 p;
        *(__half2*)&p.x = __floats2half2_rn(v.x * scale, v.y * scale);
        *(__half2*)&p.y = __floats2half2_rn(v.z * scale, v.w * scale);
        *(uint2*)(as + arow * APITCH + acg) = p;
    };
    auto loadB = [&](int kt, int st) {
        __half* bs = smem + st * STG_HALVES + BM * APITCH;
#pragma unroll
        for (int it = 0; it < 3; ++it) {
            int kr = k0 + kt * BK + br[it];
            bool p = (kr < kend);
            const __half* src = p ? (B + (size_t)kr * NCOL + bseg[it] * 8) : B;
            cp16(bs + br[it] * BPITCH + bseg[it] * 8, src, p);
        }
    };

    float4 ap[2];
    loadA(0, ap[0]); loadB(0, 0);
    asm volatile("cp.async.commit_group;\n");
    loadA(1, ap[1]); loadB(1, 1);
    asm volatile("cp.async.commit_group;\n");

    float acc[12][4] = {};
    int a_row = lane & 15;
    int a_col8 = 8 * (lane >> 4);
    int b_row = lane & 15;

    for (int kt = 0; kt < KT; ++kt) {
        asm volatile("cp.async.wait_group 1;\n");
        int st = kt % 3;
        stsA(st, ap[kt & 1]);
        __syncthreads();

        int nx = kt + 2;
        if (nx < KT) {
            loadA(nx, ap[kt & 1]);
            loadB(nx, nx % 3);
        }
        asm volatile("cp.async.commit_group;\n");

        __half* as = smem + st * STG_HALVES;
        __half* bs = as + BM * APITCH;
#pragma unroll
        for (int kk = 0; kk < 2; ++kk) {
            uint32_t a[4];
            {
                __half* p = as + (size_t)(wm * 16 + a_row) * APITCH + kk * 16 + a_col8;
                unsigned sp = (unsigned)__cvta_generic_to_shared(p);
                asm volatile("ldmatrix.sync.aligned.m8n8.x4.shared.b16 {%0,%1,%2,%3}, [%4];\n"
                             : "=r"(a[0]), "=r"(a[1]), "=r"(a[2]), "=r"(a[3]) : "r"(sp));
            }
#pragma unroll
            for (int nt = 0; nt < 12; ++nt) {
                uint32_t b0, b1;
                __half* p = bs + (size_t)(kk * 16 + b_row) * BPITCH + wn * 96 + nt * 8;
                unsigned sp = (unsigned)__cvta_generic_to_shared(p);
                asm volatile("ldmatrix.sync.aligned.m8n8.x2.trans.shared.b16 {%0,%1}, [%2];\n"
                             : "=r"(b0), "=r"(b1) : "r"(sp));
                asm volatile(
                    "mma.sync.aligned.m16n8k16.row.col.f32.f16.f16.f32 "
                    "{%0,%1,%2,%3}, {%4,%5,%6,%7}, {%8,%9}, {%0,%1,%2,%3};\n"
                    : "+f"(acc[nt][0]), "+f"(acc[nt][1]), "+f"(acc[nt][2]), "+f"(acc[nt][3])
                    : "r"(a[0]), "r"(a[1]), "r"(a[2]), "r"(a[3]), "r"(b0), "r"(b1));
            }
        }
        __syncthreads();
    }

    // epilogue
    int g = lane >> 2, tg = lane & 3;
    int r1 = row0 + wm * 16 + g;
    int r2 = r1 + 8;
    if (cfg.mode == 0) {
        __half* C = (__half*)sg.C;
#pragma unroll
        for (int nt = 0; nt < 12; ++nt) {
            int col = wn * 96 + nt * 8 + tg * 2;
            if (r1 < M) *(__half2*)(C + (size_t)r1 * NCOL + col) =
                __floats2half2_rn(acc[nt][0], acc[nt][1]);
            if (r2 < M) *(__half2*)(C + (size_t)r2 * NCOL + col) =
                __floats2half2_rn(acc[nt][2], acc[nt][3]);
        }
    } else {
        float* C = (float*)sg.C;
#pragma unroll
        for (int nt = 0; nt < 12; ++nt) {
            int col = wn * 96 + nt * 8 + tg * 2;
            if (r1 < M) {
                atomicAdd(C + (size_t)r1 * NCOL + col,     acc[nt][0]);
                atomicAdd(C + (size_t)r1 * NCOL + col + 1, acc[nt][1]);
            }
            if (r2 < M) {
                atomicAdd(C + (size_t)r2 * NCOL + col,     acc[nt][2]);
                atomicAdd(C + (size_t)r2 * NCOL + col + 1, acc[nt][3]);
            }
        }
    }
}

// ---------------- final epilogue: out = sum_j relu(Z_block_j * inv_scale + b) ----------------
__global__ void k_epilogue(const float* __restrict__ bs, float* __restrict__ out) {
    int tid = blockIdx.x * blockDim.x + threadIdx.x;
    if (tid >= NTOT * FDIM) return;
    int r = tid >> 7;
    int c = tid & 127;
    int i = (r < NL0) ? 0 : ((r < NL0 + NL1) ? 1 : 2);
    float acc = 0.0f;
#pragma unroll
    for (int j = 0; j < 3; ++j) {
        float z = g_Z[(size_t)r * NCOL + j * 128 + c] * INV_SCALE + bs[(i * 3 + j) * 128 + c];
        acc += fmaxf(z, 0.0f);
    }
    out[tid] = acc;
}

// ---------------- host launch ----------------
extern "C" void kernel_launch(void* const* d_in, const int* in_sizes, int n_in,
                              void* d_out, int out_size) {
    const float* adj0 = (const float*)d_in[0];
    const float* adj1 = (const float*)d_in[1];
    const float* adj2 = (const float*)d_in[2];
    const float* h0   = (const float*)d_in[3];
    const float* h1   = (const float*)d_in[4];
    const float* h2   = (const float*)d_in[5];
    const int*   idx0 = (const int*)d_in[6];
    const int*   idx1 = (const int*)d_in[7];
    const float* Ws   = (const float*)d_in[8];
    const float* bsp  = (const float*)d_in[9];
    float* out = (float*)d_out;

    cudaFuncSetAttribute(k_gemm, cudaFuncAttributeMaxDynamicSharedMemorySize, SMEM_BYTES);

    // device-symbol addresses (host side)
    __half* wcat_p; cudaGetSymbolAddress((void**)&wcat_p, g_wcat);
    __half* T_p;    cudaGetSymbolAddress((void**)&T_p, g_T);
    __half* Y_p;    cudaGetSymbolAddress((void**)&Y_p, g_Y);
    float*  Z_p;    cudaGetSymbolAddress((void**)&Z_p, g_Z);

    k_prep<<<5250, 256>>>(Ws);
    k_scatter_inv<<<16, 256>>>(idx0, idx1);

    // Stage 1: T_j = h_j @ Wcat_j   (M=N_j, K=128, mode 0 half store, scale 1)
    GemmCfg c1;
    c1.scale = 1.0f; c1.mode = 0;
    c1.seg[0] = { h0, wcat_p,          (char*)T_p,                          NL0, 128, 125, 1, 0   };
    c1.seg[1] = { h1, wcat_p + 49152,  (char*)(T_p + (size_t)NL0 * NCOL),   NL1, 128, 63,  1, 125 };
    c1.seg[2] = { h2, wcat_p + 98304,  (char*)(T_p + (size_t)12000 * NCOL), NL2, 128, 32,  1, 188 };
    k_gemm<<<220, 512, SMEM_BYTES>>>(c1);

    k_gather_y<<<2625, 256>>>(idx0, idx1);

    // Stage 2: Z_i = (4096*adj_i) @ Y_i   (split-K, mode 1 atomic fp32)
    GemmCfg c2;
    c2.scale = ADJ_SCALE; c2.mode = 1;
    c2.seg[0] = { adj0, Y_p,                          (char*)Z_p,                          NL0, NL0, 125, 4, 0   };
    c2.seg[1] = { adj1, Y_p + (size_t)NL0 * NCOL,     (char*)(Z_p + (size_t)NL0 * NCOL),   NL1, NL1, 63,  2, 500 };
    c2.seg[2] = { adj2, Y_p + (size_t)12000 * NCOL,   (char*)(Z_p + (size_t)12000 * NCOL), NL2, NL2, 32,  1, 626 };
    k_gemm<<<658, 512, SMEM_BYTES>>>(c2);

    k_epilogue<<<7000, 256>>>(bsp, out);
}